// round 1
// baseline (speedup 1.0000x reference)
#include <cuda_runtime.h>

#define L_LEN   4096
#define DRAD    32                  // minimum_extrema_distance (fixed for this problem)
#define NTHR    256
#define PER     (L_LEN / NTHR)      // 16 positions per thread
#define LFULL   (L_LEN + 2 * DRAD)  // padded length 4160
#define NCHUNK  (LFULL / DRAD)      // 130 chunks of 32

// dynamic smem layout:
//   Af  [LFULL] u64  : active keys (0 = decided / non-extremum), padded by 32 zeros each side
//   Sf  [LFULL] u64  : within-chunk suffix max of Af
//   Pf  [LFULL] u64  : within-chunk prefix max of Af
//   keep[L_LEN] u8   : final kept mask
#define SMEM_BYTES (3 * LFULL * 8 + L_LEN)

__device__ __forceinline__ unsigned long long umax64(unsigned long long a, unsigned long long b) {
    return a > b ? a : b;
}

__global__ void __launch_bounds__(NTHR, 1)
extrema_nms_kernel(const float* __restrict__ x, float* __restrict__ out)
{
    extern __shared__ unsigned char sraw[];
    unsigned long long* Af = (unsigned long long*)sraw;
    unsigned long long* Sf = Af + LFULL;
    unsigned long long* Pf = Sf + LFULL;
    unsigned char* keep = (unsigned char*)(Pf + LFULL);

    const int tid = threadIdx.x;
    const float* xr = x + (size_t)blockIdx.x * L_LEN;

    // zero the left/right pads of Af
    if (tid < 2 * DRAD) {
        int idx = (tid < DRAD) ? tid : (L_LEN + DRAD + (tid - DRAD));
        Af[idx] = 0ull;
    }

    // Build keys. Key = (float_bits(|x|) << 13) | (L - p)  -> descending |x|, ties by ascending p.
    // Strictly positive for any extremum; 0 for non-extrema. Unique across positions.
    float xv[PER];
    #pragma unroll
    for (int k = 0; k < PER; k++) {
        int p = tid + k * NTHR;
        float xi = xr[p];
        xv[k] = xi;
        keep[p] = 0;
        // reference pad semantics: dxr padded right with 0 (>0 false), dxl padded left with 0 (<=0 true)
        bool dxr = (p < L_LEN - 1) ? (xr[p + 1] > xi) : false;   // x[p+1] - x[p] > 0
        bool dxl = (p > 0)        ? (xi <= xr[p - 1]) : true;    // x[p] - x[p-1] <= 0
        bool ispos = (xi > 0.0f);                                // neg = !(x > 0)
        bool valley = dxr && dxl && (!ispos);
        bool peak   = (!dxr) && (!dxl) && ispos;
        unsigned long long key = 0ull;
        if (valley || peak) {
            unsigned int fb = __float_as_uint(fabsf(xi));        // |x| >= 0 -> monotonic bits
            key = (((unsigned long long)fb) << 13) | (unsigned long long)(L_LEN - p);
        }
        Af[DRAD + p] = key;
    }

    // Fixed-point rounds: kept = strict window-max among undecided; kept suppress +-DRAD.
    int safety = 0;
    while (true) {
        __syncthreads();  // Af stable (build or previous suppression complete)

        // per-chunk prefix/suffix max (chunks of 32, aligned to padded base)
        for (int c = tid; c < NCHUNK; c += NTHR) {
            int base = c * DRAD;
            unsigned long long m = 0ull;
            #pragma unroll
            for (int j = 0; j < DRAD; j++) { m = umax64(m, Af[base + j]); Pf[base + j] = m; }
            m = 0ull;
            #pragma unroll
            for (int j = DRAD - 1; j >= 0; j--) { m = umax64(m, Af[base + j]); Sf[base + j] = m; }
        }
        __syncthreads();

        // decide: window [p-32, p+32] == suffix(chunk of l) U full middle chunk U prefix(chunk of r)
        unsigned int keptmask = 0;
        #pragma unroll
        for (int k = 0; k < PER; k++) {
            int fp = tid + k * NTHR + DRAD;
            unsigned long long a = Af[fp];
            if (a) {
                int lf = fp - DRAD;          // in [0, 4095]
                int rf = fp + DRAD;          // in [64, 4159]
                unsigned long long wm = Sf[lf];
                wm = umax64(wm, Sf[((lf >> 5) + 1) << 5]);  // middle chunk max = suffix at its start
                wm = umax64(wm, Pf[rf]);
                if (a >= wm) {               // unique keys -> a is THE window max
                    keptmask |= (1u << k);
                    keep[fp - DRAD] = 1;
                }
            }
        }
        __syncthreads();  // decides done before anyone mutates Af

        // suppress: each keeper zeroes its +-32 window (keepers are pairwise > 32 apart)
        unsigned int km = keptmask;
        while (km) {
            int k = __ffs(km) - 1;
            km &= km - 1;
            int fp = tid + k * NTHR + DRAD;
            for (int q = fp - DRAD; q <= fp + DRAD; q++) Af[q] = 0ull;
        }
        __syncthreads();

        // convergence test
        int alive = 0;
        #pragma unroll
        for (int k = 0; k < PER; k++) alive |= (Af[tid + k * NTHR + DRAD] != 0ull);
        if (!__syncthreads_or(alive)) break;
        if (++safety > L_LEN) break;  // unreachable; guards against infinite loop
    }

    // write output: kept extrema keep their value, everything else 0
    float* orow = out + (size_t)blockIdx.x * L_LEN;
    #pragma unroll
    for (int k = 0; k < PER; k++) {
        int p = tid + k * NTHR;
        orow[p] = keep[p] ? xv[k] : 0.0f;
    }
}

extern "C" void kernel_launch(void* const* d_in, const int* in_sizes, int n_in,
                              void* d_out, int out_size)
{
    const float* x = (const float*)d_in[0];
    float* out = (float*)d_out;
    // d_in[1] is minimum_extrema_distance = 32 (compile-time constant DRAD)

    // opt-in to >48KB dynamic smem (idempotent, not a stream op -> capture-safe)
    cudaFuncSetAttribute(extrema_nms_kernel,
                         cudaFuncAttributeMaxDynamicSharedMemorySize, SMEM_BYTES);

    int nrows = out_size / L_LEN;   // 128
    extrema_nms_kernel<<<nrows, NTHR, SMEM_BYTES>>>(x, out);
}